// round 6
// baseline (speedup 1.0000x reference)
#include <cuda_runtime.h>

#define N_NODES 100000
#define N_EDGES 1600000
#define D_IN    128
#define D_OUT   64

// Scratch: h = x @ W   (100000 x 64 fp32 = 25.6 MB, L2-resident)
__device__ __align__(256) float g_h[N_NODES * D_OUT];

// Index-width flag: 1 = indices are int64, 0 = int32
__device__ int g_idx64;

#define XS_STRIDE 24   // 16 k-floats + 8 pad: 96B rows, 16B-aligned, conflict-free

// ---------------------------------------------------------------------------
// Kernel 1: h = x @ W  (+ probe in block 0, + zeroing `out` on the side).
// 256 threads, block tile 128 rows x 64 cols, thread tile 4 rows x 8 cols.
// Rows interleaved r*32+ty; cols split 4tx / 32+4tx  -> conflict-free LDS.
// ---------------------------------------------------------------------------
__global__ void __launch_bounds__(256) gemm_kernel(const float* __restrict__ x,
                                                   const float* __restrict__ W,
                                                   const void* __restrict__ src,
                                                   float4* __restrict__ out4) {
    __shared__ float Ws[D_IN * D_OUT];        // 32 KB, [k][col]
    __shared__ float Xs[128 * XS_STRIDE];     // 12 KB, [row][k-local]

    const int tid = threadIdx.x;

    if (blockIdx.x == 0 && tid == 0) {
        // int32 data read as u64 packs two indices -> top bits nonzero w.h.p.
        const unsigned long long* p = (const unsigned long long*)src;
        int is64 = 1;
        for (int i = 0; i < 8; i++)
            if (p[i] >= (unsigned long long)N_NODES) is64 = 0;
        g_idx64 = is64;
    }

    // Zero our slice of `out` (poisoned by harness): 8 float4 per thread.
    {
        const int base = blockIdx.x * 2048 + tid;
#pragma unroll
        for (int i = 0; i < 8; i++) {
            const int idx = base + i * 256;
            if (idx < N_NODES * D_OUT / 4)
                out4[idx] = make_float4(0.f, 0.f, 0.f, 0.f);
        }
    }

    // Load all of W: 2048 float4, 8 per thread
    {
        const float4* Wg  = (const float4*)W;
        float4*       Wsv = (float4*)Ws;
#pragma unroll
        for (int i = 0; i < 8; i++) Wsv[tid + i * 256] = Wg[tid + i * 256];
    }

    const int row0 = blockIdx.x * 128;
    const int tx = tid & 7;    // cols [4tx..4tx+3] and [32+4tx..32+4tx+3]
    const int ty = tid >> 3;   // 0..31; rows r*32+ty, r<4

    unsigned long long acc[4][4];
#pragma unroll
    for (int r = 0; r < 4; r++)
#pragma unroll
        for (int c = 0; c < 4; c++) acc[r][c] = 0ull;

    for (int k0 = 0; k0 < D_IN; k0 += 16) {
        __syncthreads();   // protect Xs from previous chunk's readers
        // Load X chunk [128 rows x 16 k]: 512 float4, 2 per thread, coalesced
#pragma unroll
        for (int i = 0; i < 2; i++) {
            const int lin  = tid + i * 256;
            const int row  = lin >> 2;
            const int slot = lin & 3;
            int grow = row0 + row;
            if (grow >= N_NODES) grow = N_NODES - 1;   // clamp (dup, unused)
            const float4 v =
                __ldg((const float4*)(x + (size_t)grow * D_IN + k0) + slot);
            *(float4*)&Xs[row * XS_STRIDE + slot * 4] = v;
        }
        __syncthreads();

#pragma unroll
        for (int kk = 0; kk < 16; kk += 4) {
            float4 xv[4];
#pragma unroll
            for (int r = 0; r < 4; r++)
                xv[r] = *(const float4*)&Xs[(r * 32 + ty) * XS_STRIDE + kk];

#pragma unroll
            for (int j = 0; j < 4; j++) {
                const ulonglong2 wvA =
                    *(const ulonglong2*)&Ws[(k0 + kk + j) * D_OUT + 4 * tx];
                const ulonglong2 wvB =
                    *(const ulonglong2*)&Ws[(k0 + kk + j) * D_OUT + 32 + 4 * tx];
#pragma unroll
                for (int r = 0; r < 4; r++) {
                    const float xs = (j == 0) ? xv[r].x : (j == 1) ? xv[r].y
                                   : (j == 2) ? xv[r].z : xv[r].w;
                    unsigned long long d;
                    asm("mov.b64 %0, {%1, %1};" : "=l"(d) : "f"(xs));
                    asm("fma.rn.f32x2 %0, %1, %2, %0;" : "+l"(acc[r][0]) : "l"(d), "l"(wvA.x));
                    asm("fma.rn.f32x2 %0, %1, %2, %0;" : "+l"(acc[r][1]) : "l"(d), "l"(wvA.y));
                    asm("fma.rn.f32x2 %0, %1, %2, %0;" : "+l"(acc[r][2]) : "l"(d), "l"(wvB.x));
                    asm("fma.rn.f32x2 %0, %1, %2, %0;" : "+l"(acc[r][3]) : "l"(d), "l"(wvB.y));
                }
            }
        }
    }

    // Store 4 rows x (4 + 4) cols
#pragma unroll
    for (int r = 0; r < 4; r++) {
        const int row = row0 + r * 32 + ty;
        if (row < N_NODES) {
            float4 lo, hi;
            asm("mov.b64 {%0, %1}, %2;" : "=f"(lo.x), "=f"(lo.y) : "l"(acc[r][0]));
            asm("mov.b64 {%0, %1}, %2;" : "=f"(lo.z), "=f"(lo.w) : "l"(acc[r][1]));
            asm("mov.b64 {%0, %1}, %2;" : "=f"(hi.x), "=f"(hi.y) : "l"(acc[r][2]));
            asm("mov.b64 {%0, %1}, %2;" : "=f"(hi.z), "=f"(hi.w) : "l"(acc[r][3]));
            *(float4*)&g_h[(size_t)row * D_OUT + 4 * tx]      = lo;
            *(float4*)&g_h[(size_t)row * D_OUT + 32 + 4 * tx] = hi;
        }
    }
}

// ---------------------------------------------------------------------------
// Kernel 2: scatter.  out[src] += w * h[dst].  16 lanes per edge (one float4
// each), 8 edges per thread: index loads batched, then 8 independent
// gather->red chains in flight.
// ---------------------------------------------------------------------------
__global__ void __launch_bounds__(256) scatter_kernel(
    const float* __restrict__ ew,
    const void* __restrict__ srcp,
    const void* __restrict__ dstp,
    float* __restrict__ out) {

    const int t  = blockIdx.x * 256 + threadIdx.x;   // 3.2M threads, exact
    const int c  = t & 15;                           // float4 slot in row
    const int g  = t >> 4;                           // edge octet
    const int e0 = 8 * g;

    const int idx64 = g_idx64;

    const int* sp = (const int*)srcp;
    const int* dp = (const int*)dstp;

    int s[8], d[8];
    float w[8];
#pragma unroll
    for (int i = 0; i < 8; i++) {
        const int e = e0 + i;
        if (idx64) {                 // little-endian low words of int64
            s[i] = __ldg(sp + 2 * e);
            d[i] = __ldg(dp + 2 * e);
        } else {
            s[i] = __ldg(sp + e);
            d[i] = __ldg(dp + e);
        }
        w[i] = __ldg(ew + e);
    }

    float4 v[8];
#pragma unroll
    for (int i = 0; i < 8; i++)
        v[i] = __ldg((const float4*)(g_h + (size_t)d[i] * D_OUT) + c);

#pragma unroll
    for (int i = 0; i < 8; i++) {
        if ((unsigned)s[i] < N_NODES) {
            float* p = out + (size_t)s[i] * D_OUT + 4 * c;
            asm volatile("red.global.add.v4.f32 [%0], {%1, %2, %3, %4};"
                         :: "l"(p), "f"(v[i].x * w[i]), "f"(v[i].y * w[i]),
                            "f"(v[i].z * w[i]), "f"(v[i].w * w[i]) : "memory");
        }
    }
}

// ---------------------------------------------------------------------------
// Kernel 3: in-place ReLU, 2 float4 per thread
// ---------------------------------------------------------------------------
#define RELU_HALF (N_NODES * D_OUT / 4 / 2)   // 800000 float4 per half

__global__ void __launch_bounds__(256) relu_kernel(float4* __restrict__ out) {
    const int i = blockIdx.x * 256 + threadIdx.x;
    float4 a = out[i];
    float4 b = out[i + RELU_HALF];
    a.x = fmaxf(a.x, 0.f); a.y = fmaxf(a.y, 0.f);
    a.z = fmaxf(a.z, 0.f); a.w = fmaxf(a.w, 0.f);
    b.x = fmaxf(b.x, 0.f); b.y = fmaxf(b.y, 0.f);
    b.z = fmaxf(b.z, 0.f); b.w = fmaxf(b.w, 0.f);
    out[i] = a;
    out[i + RELU_HALF] = b;
}

// ---------------------------------------------------------------------------
extern "C" void kernel_launch(void* const* d_in, const int* in_sizes, int n_in,
                              void* d_out, int out_size) {
    const float* x   = (const float*)d_in[0];      // [100000, 128]
    const float* ew  = (const float*)d_in[1];      // [1600000]
    const float* W   = (const float*)d_in[2];      // [128, 64]
    const void*  src = d_in[3];                    // [1600000] int64/int32
    const void*  dst = d_in[4];                    // [1600000] int64/int32
    float* out = (float*)d_out;                    // [100000, 64]

    // h = x @ W (+probe +zero-out): ceil(100000/128) = 782 blocks
    gemm_kernel<<<(N_NODES + 127) / 128, 256>>>(x, W, src, (float4*)out);

    // scatter: E/8 groups * 16 lanes = 3.2M threads -> 12500 blocks
    scatter_kernel<<<(N_EDGES * 2) / 256, 256>>>(ew, src, dst, out);

    // ReLU: 800000 threads -> 3125 blocks
    relu_kernel<<<RELU_HALF / 256, 256>>>((float4*)out);
}